// round 8
// baseline (speedup 1.0000x reference)
#include <cuda_runtime.h>
#include <cstdint>

// DynamicRouting (R7): mma.sync tf32, con kept entirely in REGISTERS
// (acc[8][2][4] per thread). SMEM only holds X/W tiles (double-buffered),
// tiny Gram partials, and alphas. 256 thr, 2 CTAs/SM.

namespace {
constexpr int Gn   = 8;
constexpr int FIn  = 64;
constexpr int FOn  = 64;
constexpr int HWn  = 4096;
constexpr int Bn   = 16;
constexpr int PXT  = 32;
constexpr int THREADS = 256;

constexpr int SXs = 40;             // X [fi][px] : bank = (8*fi + px) % 32
constexpr int SWs = 68;             // W [fo][fi] : bank = (4*fo + fi) % 32

constexpr int X0o = 0;                         // 64*40 = 2560 w
constexpr int X1o = X0o + FIn * SXs;           // 2560
constexpr int W0o = X1o + FIn * SXs;           // 5120   (64*68 = 4352 w)
constexpr int W1o = W0o + FOn * SWs;           // 9472
constexpr int GRo = W1o + FOn * SWs;           // 13824  (4 foq * 32 px * 36)
constexpr int ALo = GRo + 4 * PXT * 36;        // 18432  (8 g * 32 px)
constexpr int SMEM_WORDS = ALo + Gn * PXT;     // 18688
constexpr int SMEM_BYTES = SMEM_WORDS * 4;     // 74752 B -> 2 CTAs/SM
}

__device__ __forceinline__ uint32_t cvt_tf32(float f) {
    uint32_t r;
    asm("cvt.rna.tf32.f32 %0, %1;" : "=r"(r) : "f"(f));
    return r;
}

__device__ __forceinline__ void mma_tf32(float c[4],
                                         uint32_t a0, uint32_t a1,
                                         uint32_t a2, uint32_t a3,
                                         uint32_t b0, uint32_t b1) {
    asm volatile(
        "mma.sync.aligned.m16n8k8.row.col.f32.tf32.tf32.f32 "
        "{%0,%1,%2,%3}, {%4,%5,%6,%7}, {%8,%9}, {%0,%1,%2,%3};"
        : "+f"(c[0]), "+f"(c[1]), "+f"(c[2]), "+f"(c[3])
        : "r"(a0), "r"(a1), "r"(a2), "r"(a3), "r"(b0), "r"(b1));
}

__device__ __forceinline__ float sigmoidf_(float v) {
    return 1.f / (1.f + __expf(-v));
}

__device__ __forceinline__ int pidx(int a, int b) {
    int lo = a < b ? a : b, hi = a < b ? b : a;
    return lo * 8 - lo * (lo - 1) / 2 + (hi - lo);
}

__global__ void __launch_bounds__(THREADS, 2)
dynrout_mma_kernel(const float* __restrict__ x,
                   const float* __restrict__ w,
                   const float* __restrict__ bias,
                   float* __restrict__ out)
{
    extern __shared__ uint32_t smu[];
    float* smf = reinterpret_cast<float*>(smu);

    const int t    = threadIdx.x;
    const int wid  = t >> 5;
    const int lane = t & 31;
    const int gid  = lane >> 2;
    const int tid4 = lane & 3;

    const int cta = blockIdx.x;
    const int bi  = cta >> 7;
    const int p0  = (cta & 127) * PXT;

    // warp tile: 16 px x 16 fo
    const int pxb = (wid & 1) * 16;
    const int fob = (wid >> 1) * 16;
    const int foq = wid >> 1;

    // ---------------- gmem prefetch into registers ---------------------------
    float4 rx[2], rw[4];
    auto load_regs = [&](int g) {
        const float* xg = x + ((size_t)(bi * Gn + g) * FIn) * HWn + p0;
        const float* wg = w + (size_t)g * FOn * FIn;
        #pragma unroll
        for (int k = 0; k < 2; k++) {
            int q  = t + k * THREADS;
            int fi = q >> 3;
            int c4 = q & 7;
            rx[k] = *reinterpret_cast<const float4*>(xg + (size_t)fi * HWn + c4 * 4);
        }
        #pragma unroll
        for (int k = 0; k < 4; k++) {
            int q  = t + k * THREADS;
            int fo = q >> 4;
            int c4 = q & 15;
            rw[k] = *reinterpret_cast<const float4*>(wg + fo * FIn + c4 * 4);
        }
    };
    auto store_regs = [&](int buf) {
        const int xo = buf ? X1o : X0o;
        const int wo = buf ? W1o : W0o;
        #pragma unroll
        for (int k = 0; k < 2; k++) {
            int q  = t + k * THREADS;
            int fi = q >> 3;
            int c4 = q & 7;
            uint4 xv = make_uint4(cvt_tf32(rx[k].x), cvt_tf32(rx[k].y),
                                  cvt_tf32(rx[k].z), cvt_tf32(rx[k].w));
            *reinterpret_cast<uint4*>(&smu[xo + fi * SXs + c4 * 4]) = xv;
        }
        #pragma unroll
        for (int k = 0; k < 4; k++) {
            int q  = t + k * THREADS;
            int fo = q >> 4;
            int c4 = q & 15;
            uint4 wv = make_uint4(cvt_tf32(rw[k].x), cvt_tf32(rw[k].y),
                                  cvt_tf32(rw[k].z), cvt_tf32(rw[k].w));
            *reinterpret_cast<uint4*>(&smu[wo + fo * SWs + c4 * 4]) = wv;
        }
    };

    // ---------------- GEMM: all 8 groups accumulate in registers -------------
    float acc[Gn][2][4];
    #pragma unroll
    for (int g = 0; g < Gn; g++)
        #pragma unroll
        for (int n = 0; n < 2; n++)
            #pragma unroll
            for (int j = 0; j < 4; j++) acc[g][n][j] = 0.f;

    load_regs(0);
    store_regs(0);
    __syncthreads();

    for (int g = 0; g < Gn; g++) {
        if (g + 1 < Gn) load_regs(g + 1);

        const int xo = (g & 1) ? X1o : X0o;
        const int wo = (g & 1) ? W1o : W0o;

        #pragma unroll
        for (int s = 0; s < 8; s++) {
            const int fi0 = s * 8;
            uint32_t a0 = smu[xo + (fi0 + tid4)     * SXs + pxb + gid];
            uint32_t a1 = smu[xo + (fi0 + tid4)     * SXs + pxb + gid + 8];
            uint32_t a2 = smu[xo + (fi0 + 4 + tid4) * SXs + pxb + gid];
            uint32_t a3 = smu[xo + (fi0 + 4 + tid4) * SXs + pxb + gid + 8];
            #pragma unroll
            for (int n = 0; n < 2; n++) {
                int fo = fob + n * 8 + gid;
                uint32_t b0 = smu[wo + fo * SWs + fi0 + tid4];
                uint32_t b1 = smu[wo + fo * SWs + fi0 + 4 + tid4];
                mma_tf32(acc[g][n], a0, a1, a2, a3, b0, b1);
            }
        }

        if (g + 1 < Gn) store_regs((g + 1) & 1);
        __syncthreads();
    }

    // ---------------- Gram partials from registers ---------------------------
    // acc[g][n][0/1] -> px = pxb+gid,   fo = fob+n*8+2*tid4 (+1)
    // acc[g][n][2/3] -> px = pxb+gid+8, same fo
    #pragma unroll
    for (int r = 0; r < 2; r++) {
        float P[36];
        #pragma unroll
        for (int p = 0; p < 36; p++) P[p] = 0.f;

        #pragma unroll
        for (int n = 0; n < 2; n++)
            #pragma unroll
            for (int jj = 0; jj < 2; jj++) {
                float cg[Gn];
                #pragma unroll
                for (int g = 0; g < Gn; g++) cg[g] = acc[g][n][2 * r + jj];
                int p = 0;
                #pragma unroll
                for (int a = 0; a < Gn; a++)
                    #pragma unroll
                    for (int b = a; b < Gn; b++)
                        P[p++] += cg[a] * cg[b];
            }
        // butterfly over tid4: all lanes end with the 16-fo warp partial
        #pragma unroll
        for (int p = 0; p < 36; p++) {
            P[p] += __shfl_xor_sync(0xFFFFFFFFu, P[p], 1);
            P[p] += __shfl_xor_sync(0xFFFFFFFFu, P[p], 2);
        }
        // lane tid4 stores pairs [9*tid4, 9*tid4+9)   (conflict-free banks)
        const int pxl = pxb + gid + 8 * r;
        #pragma unroll
        for (int k = 0; k < 9; k++) {
            int p = 9 * tid4 + k;
            smf[GRo + (foq * PXT + pxl) * 36 + p] = P[p];
        }
    }
    __syncthreads();

    // ---------------- routing (32 threads, one per pixel) --------------------
    if (t < PXT) {
        const int px = t;
        float G[36];
        #pragma unroll
        for (int p = 0; p < 36; p++) {
            float s = 0.f;
            #pragma unroll
            for (int q = 0; q < 4; q++)
                s += smf[GRo + (q * PXT + px) * 36 + p];
            G[p] = s;
        }
        float beta[Gn], alpha[Gn];
        #pragma unroll
        for (int g = 0; g < Gn; g++) {
            float s = 0.f;
            #pragma unroll
            for (int g2 = 0; g2 < Gn; g2++) s += G[pidx(g2, g)];
            beta[g] = 0.5f * s;
        }
        #pragma unroll
        for (int g = 0; g < Gn; g++) alpha[g] = sigmoidf_(beta[g]);
        #pragma unroll
        for (int g = 0; g < Gn; g++) {
            float s = 0.f;
            #pragma unroll
            for (int g2 = 0; g2 < Gn; g2++) s += alpha[g2] * G[pidx(g2, g)];
            beta[g] += s;
        }
        #pragma unroll
        for (int g = 0; g < Gn; g++)
            smf[ALo + g * PXT + px] = sigmoidf_(beta[g]);
    }
    __syncthreads();

    // ---------------- final: out = sum_g alpha*con + bias (from regs) --------
    {
        float* ob = out + (size_t)bi * FOn * HWn + p0;
        #pragma unroll
        for (int r = 0; r < 2; r++) {
            const int pxl = pxb + gid + 8 * r;
            float al[Gn];
            #pragma unroll
            for (int g = 0; g < Gn; g++) al[g] = smf[ALo + g * PXT + pxl];
            #pragma unroll
            for (int n = 0; n < 2; n++) {
                #pragma unroll
                for (int jj = 0; jj < 2; jj++) {
                    float s = 0.f;
                    #pragma unroll
                    for (int g = 0; g < Gn; g++)
                        s += al[g] * acc[g][n][2 * r + jj];
                    int fo = fob + n * 8 + 2 * tid4 + jj;
                    ob[(size_t)fo * HWn + pxl] = s + __ldg(&bias[fo]);
                }
            }
        }
    }
}

extern "C" void kernel_launch(void* const* d_in, const int* in_sizes, int n_in,
                              void* d_out, int out_size)
{
    const float* x = nullptr;
    const float* w = nullptr;
    const float* b = nullptr;
    for (int i = 0; i < n_in; i++) {
        if (in_sizes[i] == Bn * Gn * FIn * HWn)      x = (const float*)d_in[i];
        else if (in_sizes[i] == Gn * FOn * FIn)      w = (const float*)d_in[i];
        else if (in_sizes[i] == FOn)                 b = (const float*)d_in[i];
    }
    float* out = (float*)d_out;

    static bool attr_set = false;
    if (!attr_set) {
        cudaFuncSetAttribute(dynrout_mma_kernel,
                             cudaFuncAttributeMaxDynamicSharedMemorySize, SMEM_BYTES);
        attr_set = true;
    }

    const int n_ctas = (Bn * HWn) / PXT;   // 2048
    dynrout_mma_kernel<<<n_ctas, THREADS, SMEM_BYTES>>>(x, w, b, out);
}

// round 9
// speedup vs baseline: 1.0473x; 1.0473x over previous
#include <cuda_runtime.h>
#include <cstdint>

// DynamicRouting (R8): R7 (con in registers) + Gram computed in 3 chunks of 12
// pairs to keep peak live registers ~100 (no spills at launch_bounds(256,2)).

namespace {
constexpr int Gn   = 8;
constexpr int FIn  = 64;
constexpr int FOn  = 64;
constexpr int HWn  = 4096;
constexpr int Bn   = 16;
constexpr int PXT  = 32;
constexpr int THREADS = 256;

constexpr int SXs = 40;             // X [fi][px] : bank = (8*fi + px) % 32
constexpr int SWs = 68;             // W [fo][fi] : bank = (4*fo + fi) % 32

constexpr int X0o = 0;                         // 64*40 = 2560 w
constexpr int X1o = X0o + FIn * SXs;           // 2560
constexpr int W0o = X1o + FIn * SXs;           // 5120   (64*68 = 4352 w)
constexpr int W1o = W0o + FOn * SWs;           // 9472
constexpr int GRo = W1o + FOn * SWs;           // 13824  (4 foq * 32 px * 36)
constexpr int ALo = GRo + 4 * PXT * 36;        // 18432  (8 g * 32 px)
constexpr int SMEM_WORDS = ALo + Gn * PXT;     // 18688
constexpr int SMEM_BYTES = SMEM_WORDS * 4;     // 74752 B -> 2 CTAs/SM

// symmetric pair tables (a<=b), 36 pairs in pidx order
__device__ __constant__ const int kPA[36] = {
    0,0,0,0,0,0,0,0, 1,1,1,1,1,1,1, 2,2,2,2,2,2, 3,3,3,3,3,
    4,4,4,4, 5,5,5, 6,6, 7};
__device__ __constant__ const int kPB[36] = {
    0,1,2,3,4,5,6,7, 1,2,3,4,5,6,7, 2,3,4,5,6,7, 3,4,5,6,7,
    4,5,6,7, 5,6,7, 6,7, 7};
}

__device__ __forceinline__ uint32_t cvt_tf32(float f) {
    uint32_t r;
    asm("cvt.rna.tf32.f32 %0, %1;" : "=r"(r) : "f"(f));
    return r;
}

__device__ __forceinline__ void mma_tf32(float c[4],
                                         uint32_t a0, uint32_t a1,
                                         uint32_t a2, uint32_t a3,
                                         uint32_t b0, uint32_t b1) {
    asm volatile(
        "mma.sync.aligned.m16n8k8.row.col.f32.tf32.tf32.f32 "
        "{%0,%1,%2,%3}, {%4,%5,%6,%7}, {%8,%9}, {%0,%1,%2,%3};"
        : "+f"(c[0]), "+f"(c[1]), "+f"(c[2]), "+f"(c[3])
        : "r"(a0), "r"(a1), "r"(a2), "r"(a3), "r"(b0), "r"(b1));
}

__device__ __forceinline__ float sigmoidf_(float v) {
    return 1.f / (1.f + __expf(-v));
}

__device__ __forceinline__ int pidx(int a, int b) {
    int lo = a < b ? a : b, hi = a < b ? b : a;
    return lo * 8 - lo * (lo - 1) / 2 + (hi - lo);
}

__global__ void __launch_bounds__(THREADS, 2)
dynrout_mma_kernel(const float* __restrict__ x,
                   const float* __restrict__ w,
                   const float* __restrict__ bias,
                   float* __restrict__ out)
{
    extern __shared__ uint32_t smu[];
    float* smf = reinterpret_cast<float*>(smu);

    const int t    = threadIdx.x;
    const int wid  = t >> 5;
    const int lane = t & 31;
    const int gid  = lane >> 2;
    const int tid4 = lane & 3;

    const int cta = blockIdx.x;
    const int bi  = cta >> 7;
    const int p0  = (cta & 127) * PXT;

    const int pxb = (wid & 1) * 16;
    const int fob = (wid >> 1) * 16;
    const int foq = wid >> 1;

    // ---------------- gmem prefetch into registers ---------------------------
    float4 rx[2], rw[4];
    auto load_regs = [&](int g) {
        const float* xg = x + ((size_t)(bi * Gn + g) * FIn) * HWn + p0;
        const float* wg = w + (size_t)g * FOn * FIn;
        #pragma unroll
        for (int k = 0; k < 2; k++) {
            int q  = t + k * THREADS;
            int fi = q >> 3;
            int c4 = q & 7;
            rx[k] = *reinterpret_cast<const float4*>(xg + (size_t)fi * HWn + c4 * 4);
        }
        #pragma unroll
        for (int k = 0; k < 4; k++) {
            int q  = t + k * THREADS;
            int fo = q >> 4;
            int c4 = q & 15;
            rw[k] = *reinterpret_cast<const float4*>(wg + fo * FIn + c4 * 4);
        }
    };
    auto store_regs = [&](int buf) {
        const int xo = buf ? X1o : X0o;
        const int wo = buf ? W1o : W0o;
        #pragma unroll
        for (int k = 0; k < 2; k++) {
            int q  = t + k * THREADS;
            int fi = q >> 3;
            int c4 = q & 7;
            uint4 xv = make_uint4(cvt_tf32(rx[k].x), cvt_tf32(rx[k].y),
                                  cvt_tf32(rx[k].z), cvt_tf32(rx[k].w));
            *reinterpret_cast<uint4*>(&smu[xo + fi * SXs + c4 * 4]) = xv;
        }
        #pragma unroll
        for (int k = 0; k < 4; k++) {
            int q  = t + k * THREADS;
            int fo = q >> 4;
            int c4 = q & 15;
            uint4 wv = make_uint4(cvt_tf32(rw[k].x), cvt_tf32(rw[k].y),
                                  cvt_tf32(rw[k].z), cvt_tf32(rw[k].w));
            *reinterpret_cast<uint4*>(&smu[wo + fo * SWs + c4 * 4]) = wv;
        }
    };

    // ---------------- GEMM: all 8 groups accumulate in registers -------------
    float acc[Gn][2][4];
    #pragma unroll
    for (int g = 0; g < Gn; g++)
        #pragma unroll
        for (int n = 0; n < 2; n++)
            #pragma unroll
            for (int j = 0; j < 4; j++) acc[g][n][j] = 0.f;

    load_regs(0);
    store_regs(0);
    __syncthreads();

    for (int g = 0; g < Gn; g++) {
        if (g + 1 < Gn) load_regs(g + 1);

        const int xo = (g & 1) ? X1o : X0o;
        const int wo = (g & 1) ? W1o : W0o;

        #pragma unroll
        for (int s = 0; s < 8; s++) {
            const int fi0 = s * 8;
            uint32_t a0 = smu[xo + (fi0 + tid4)     * SXs + pxb + gid];
            uint32_t a1 = smu[xo + (fi0 + tid4)     * SXs + pxb + gid + 8];
            uint32_t a2 = smu[xo + (fi0 + 4 + tid4) * SXs + pxb + gid];
            uint32_t a3 = smu[xo + (fi0 + 4 + tid4) * SXs + pxb + gid + 8];
            #pragma unroll
            for (int n = 0; n < 2; n++) {
                int fo = fob + n * 8 + gid;
                uint32_t b0 = smu[wo + fo * SWs + fi0 + tid4];
                uint32_t b1 = smu[wo + fo * SWs + fi0 + 4 + tid4];
                mma_tf32(acc[g][n], a0, a1, a2, a3, b0, b1);
            }
        }

        if (g + 1 < Gn) store_regs((g + 1) & 1);
        __syncthreads();
    }

    // ---------------- Gram partials from registers (3 chunks of 12) ----------
    // acc[g][n][0/1] -> px = pxb+gid,   acc[g][n][2/3] -> px = pxb+gid+8
    #pragma unroll
    for (int r = 0; r < 2; r++) {
        const int pxl = pxb + gid + 8 * r;
        #pragma unroll
        for (int c = 0; c < 3; c++) {
            float P[12];
            #pragma unroll
            for (int k = 0; k < 12; k++) P[k] = 0.f;

            #pragma unroll
            for (int n = 0; n < 2; n++)
                #pragma unroll
                for (int jj = 0; jj < 2; jj++) {
                    float cg[Gn];
                    #pragma unroll
                    for (int g = 0; g < Gn; g++) cg[g] = acc[g][n][2 * r + jj];
                    #pragma unroll
                    for (int k = 0; k < 12; k++)
                        P[k] += cg[kPA[c * 12 + k]] * cg[kPB[c * 12 + k]];
                }
            // butterfly over tid4 -> full 16-fo warp partial in every lane
            #pragma unroll
            for (int k = 0; k < 12; k++) {
                P[k] += __shfl_xor_sync(0xFFFFFFFFu, P[k], 1);
                P[k] += __shfl_xor_sync(0xFFFFFFFFu, P[k], 2);
            }
            // lane tid4 stores 3 of the 12 (conflict-free banks)
            #pragma unroll
            for (int m = 0; m < 3; m++) {
                int k = 3 * tid4 + m;
                smf[GRo + (foq * PXT + pxl) * 36 + c * 12 + k] = P[k];
            }
        }
    }
    __syncthreads();

    // ---------------- routing (32 threads, one per pixel) --------------------
    if (t < PXT) {
        const int px = t;
        float G[36];
        #pragma unroll
        for (int p = 0; p < 36; p++) {
            float s = 0.f;
            #pragma unroll
            for (int q = 0; q < 4; q++)
                s += smf[GRo + (q * PXT + px) * 36 + p];
            G[p] = s;
        }
        float beta[Gn], alpha[Gn];
        #pragma unroll
        for (int g = 0; g < Gn; g++) {
            float s = 0.f;
            #pragma unroll
            for (int g2 = 0; g2 < Gn; g2++) s += G[pidx(g2, g)];
            beta[g] = 0.5f * s;
        }
        #pragma unroll
        for (int g = 0; g < Gn; g++) alpha[g] = sigmoidf_(beta[g]);
        #pragma unroll
        for (int g = 0; g < Gn; g++) {
            float s = 0.f;
            #pragma unroll
            for (int g2 = 0; g2 < Gn; g2++) s += alpha[g2] * G[pidx(g2, g)];
            beta[g] += s;
        }
        #pragma unroll
        for (int g = 0; g < Gn; g++)
            smf[ALo + g * PXT + px] = sigmoidf_(beta[g]);
    }
    __syncthreads();

    // ---------------- final: out = sum_g alpha*con + bias (from regs) --------
    {
        float* ob = out + (size_t)bi * FOn * HWn + p0;
        #pragma unroll
        for (int r = 0; r < 2; r++) {
            const int pxl = pxb + gid + 8 * r;
            float al[Gn];
            #pragma unroll
            for (int g = 0; g < Gn; g++) al[g] = smf[ALo + g * PXT + pxl];
            #pragma unroll
            for (int n = 0; n < 2; n++) {
                #pragma unroll
                for (int jj = 0; jj < 2; jj++) {
                    float s = 0.f;
                    #pragma unroll
                    for (int g = 0; g < Gn; g++)
                        s += al[g] * acc[g][n][2 * r + jj];
                    int fo = fob + n * 8 + 2 * tid4 + jj;
                    ob[(size_t)fo * HWn + pxl] = s + __ldg(&bias[fo]);
                }
            }
        }
    }
}

extern "C" void kernel_launch(void* const* d_in, const int* in_sizes, int n_in,
                              void* d_out, int out_size)
{
    const float* x = nullptr;
    const float* w = nullptr;
    const float* b = nullptr;
    for (int i = 0; i < n_in; i++) {
        if (in_sizes[i] == Bn * Gn * FIn * HWn)      x = (const float*)d_in[i];
        else if (in_sizes[i] == Gn * FOn * FIn)      w = (const float*)d_in[i];
        else if (in_sizes[i] == FOn)                 b = (const float*)d_in[i];
    }
    float* out = (float*)d_out;

    static bool attr_set = false;
    if (!attr_set) {
        cudaFuncSetAttribute(dynrout_mma_kernel,
                             cudaFuncAttributeMaxDynamicSharedMemorySize, SMEM_BYTES);
        attr_set = true;
    }

    const int n_ctas = (Bn * HWn) / PXT;   // 2048
    dynrout_mma_kernel<<<n_ctas, THREADS, SMEM_BYTES>>>(x, w, b, out);
}

// round 10
// speedup vs baseline: 1.0601x; 1.0122x over previous
#include <cuda_runtime.h>
#include <cstdint>

// DynamicRouting (R9): con in registers + cp.async gmem->SMEM (no prefetch
// registers -> no spills). mma.sync tf32, Gram routing. 256 thr, 2 CTAs/SM.

namespace {
constexpr int Gn   = 8;
constexpr int FIn  = 64;
constexpr int FOn  = 64;
constexpr int HWn  = 4096;
constexpr int Bn   = 16;
constexpr int PXT  = 32;
constexpr int THREADS = 256;

constexpr int SXs = 40;             // X [fi][px] raw fp32 : bank = (8*fi+px)%32
constexpr int SWs = 68;             // W [fo][fi] raw fp32 : bank = (4*fo+fi)%32

constexpr int X0o = 0;                         // 64*40 = 2560 w
constexpr int X1o = X0o + FIn * SXs;           // 2560
constexpr int W0o = X1o + FIn * SXs;           // 5120   (64*68 = 4352 w)
constexpr int W1o = W0o + FOn * SWs;           // 9472
constexpr int GRo = W1o + FOn * SWs;           // 13824  (4 foq * 32 px * 36)
constexpr int ALo = GRo + 4 * PXT * 36;        // 18432  (8 g * 32 px)
constexpr int SMEM_WORDS = ALo + Gn * PXT;     // 18688
constexpr int SMEM_BYTES = SMEM_WORDS * 4;     // 74752 B -> 2 CTAs/SM

// symmetric pair tables (a<=b), 36 pairs in pidx order
__device__ __constant__ const int kPA[36] = {
    0,0,0,0,0,0,0,0, 1,1,1,1,1,1,1, 2,2,2,2,2,2, 3,3,3,3,3,
    4,4,4,4, 5,5,5, 6,6, 7};
__device__ __constant__ const int kPB[36] = {
    0,1,2,3,4,5,6,7, 1,2,3,4,5,6,7, 2,3,4,5,6,7, 3,4,5,6,7,
    4,5,6,7, 5,6,7, 6,7, 7};
}

__device__ __forceinline__ uint32_t cvt_tf32(float f) {
    uint32_t r;
    asm("cvt.rna.tf32.f32 %0, %1;" : "=r"(r) : "f"(f));
    return r;
}

__device__ __forceinline__ uint32_t smem_u32(const void* p) {
    uint32_t a;
    asm("{ .reg .u64 t; cvta.to.shared.u64 t, %1; cvt.u32.u64 %0, t; }"
        : "=r"(a) : "l"(p));
    return a;
}

__device__ __forceinline__ void cp16(uint32_t dst, const void* src) {
    asm volatile("cp.async.cg.shared.global [%0], [%1], 16;"
                 :: "r"(dst), "l"(src) : "memory");
}

__device__ __forceinline__ void mma_tf32(float c[4],
                                         uint32_t a0, uint32_t a1,
                                         uint32_t a2, uint32_t a3,
                                         uint32_t b0, uint32_t b1) {
    asm volatile(
        "mma.sync.aligned.m16n8k8.row.col.f32.tf32.tf32.f32 "
        "{%0,%1,%2,%3}, {%4,%5,%6,%7}, {%8,%9}, {%0,%1,%2,%3};"
        : "+f"(c[0]), "+f"(c[1]), "+f"(c[2]), "+f"(c[3])
        : "r"(a0), "r"(a1), "r"(a2), "r"(a3), "r"(b0), "r"(b1));
}

__device__ __forceinline__ float sigmoidf_(float v) {
    return 1.f / (1.f + __expf(-v));
}

__device__ __forceinline__ int pidx(int a, int b) {
    int lo = a < b ? a : b, hi = a < b ? b : a;
    return lo * 8 - lo * (lo - 1) / 2 + (hi - lo);
}

__global__ void __launch_bounds__(THREADS, 2)
dynrout_mma_kernel(const float* __restrict__ x,
                   const float* __restrict__ w,
                   const float* __restrict__ bias,
                   float* __restrict__ out)
{
    extern __shared__ uint32_t smu[];
    float* smf = reinterpret_cast<float*>(smu);
    const uint32_t sbase = smem_u32(smu);

    const int t    = threadIdx.x;
    const int wid  = t >> 5;
    const int lane = t & 31;
    const int gid  = lane >> 2;
    const int tid4 = lane & 3;

    const int cta = blockIdx.x;
    const int bi  = cta >> 7;
    const int p0  = (cta & 127) * PXT;

    const int pxb = (wid & 1) * 16;     // px half
    const int fob = (wid >> 1) * 16;    // fo quarter
    const int foq = wid >> 1;

    // per-thread cp.async chunk coordinates (fixed across groups)
    const int xq_fi  = t >> 3;          // X: 512 chunks -> 2/thread
    const int xq_c4  = (t & 7) * 4;
    const int xq_fi2 = (t + THREADS) >> 3;
    const int xq_c42 = ((t + THREADS) & 7) * 4;

    const float* xg0 = x + ((size_t)bi * Gn * FIn) * HWn + p0;
    const float* wg0 = w;

    auto issue_group = [&](int g, int buf) {
        const float* xg = xg0 + (size_t)g * FIn * HWn;
        const float* wg = wg0 + (size_t)g * FOn * FIn;
        const uint32_t xo = sbase + (buf ? X1o : X0o) * 4;
        const uint32_t wo = sbase + (buf ? W1o : W0o) * 4;
        cp16(xo + (xq_fi  * SXs + xq_c4)  * 4, xg + (size_t)xq_fi  * HWn + xq_c4);
        cp16(xo + (xq_fi2 * SXs + xq_c42) * 4, xg + (size_t)xq_fi2 * HWn + xq_c42);
        #pragma unroll
        for (int k = 0; k < 4; k++) {           // W: 1024 chunks -> 4/thread
            int q  = t + k * THREADS;
            int fo = q >> 4;
            int c4 = (q & 15) * 4;
            cp16(wo + (fo * SWs + c4) * 4, wg + fo * FIn + c4);
        }
        asm volatile("cp.async.commit_group;" ::: "memory");
    };

    // ---------------- GEMM: all 8 groups accumulate in registers -------------
    float acc[Gn][2][4];
    #pragma unroll
    for (int g = 0; g < Gn; g++)
        #pragma unroll
        for (int n = 0; n < 2; n++)
            #pragma unroll
            for (int j = 0; j < 4; j++) acc[g][n][j] = 0.f;

    issue_group(0, 0);

    for (int g = 0; g < Gn; g++) {
        if (g + 1 < Gn) issue_group(g + 1, (g + 1) & 1);

        if (g < 7) asm volatile("cp.async.wait_group 1;" ::: "memory");
        else       asm volatile("cp.async.wait_group 0;" ::: "memory");
        __syncthreads();

        const int xo = (g & 1) ? X1o : X0o;
        const int wo = (g & 1) ? W1o : W0o;

        #pragma unroll
        for (int s = 0; s < 8; s++) {
            const int fi0 = s * 8;
            uint32_t a0 = cvt_tf32(smf[xo + (fi0 + tid4)     * SXs + pxb + gid]);
            uint32_t a1 = cvt_tf32(smf[xo + (fi0 + tid4)     * SXs + pxb + gid + 8]);
            uint32_t a2 = cvt_tf32(smf[xo + (fi0 + 4 + tid4) * SXs + pxb + gid]);
            uint32_t a3 = cvt_tf32(smf[xo + (fi0 + 4 + tid4) * SXs + pxb + gid + 8]);
            #pragma unroll
            for (int n = 0; n < 2; n++) {
                int fo = fob + n * 8 + gid;
                uint32_t b0 = cvt_tf32(smf[wo + fo * SWs + fi0 + tid4]);
                uint32_t b1 = cvt_tf32(smf[wo + fo * SWs + fi0 + 4 + tid4]);
                mma_tf32(acc[g][n], a0, a1, a2, a3, b0, b1);
            }
        }
        __syncthreads();    // done reading this buffer (reused at g+2)
    }

    // ---------------- Gram partials from registers (3 chunks of 12) ----------
    // acc[g][n][0/1] -> px = pxb+gid,   acc[g][n][2/3] -> px = pxb+gid+8
    #pragma unroll
    for (int r = 0; r < 2; r++) {
        const int pxl = pxb + gid + 8 * r;
        #pragma unroll
        for (int c = 0; c < 3; c++) {
            float P[12];
            #pragma unroll
            for (int k = 0; k < 12; k++) P[k] = 0.f;

            #pragma unroll
            for (int n = 0; n < 2; n++)
                #pragma unroll
                for (int jj = 0; jj < 2; jj++) {
                    float cg[Gn];
                    #pragma unroll
                    for (int g = 0; g < Gn; g++) cg[g] = acc[g][n][2 * r + jj];
                    #pragma unroll
                    for (int k = 0; k < 12; k++)
                        P[k] += cg[kPA[c * 12 + k]] * cg[kPB[c * 12 + k]];
                }
            #pragma unroll
            for (int k = 0; k < 12; k++) {
                P[k] += __shfl_xor_sync(0xFFFFFFFFu, P[k], 1);
                P[k] += __shfl_xor_sync(0xFFFFFFFFu, P[k], 2);
            }
            #pragma unroll
            for (int m = 0; m < 3; m++) {
                int k = 3 * tid4 + m;
                smf[GRo + (foq * PXT + pxl) * 36 + c * 12 + k] = P[k];
            }
        }
    }
    __syncthreads();

    // ---------------- routing (32 threads, one per pixel) --------------------
    if (t < PXT) {
        const int px = t;
        float G[36];
        #pragma unroll
        for (int p = 0; p < 36; p++) {
            float s = 0.f;
            #pragma unroll
            for (int q = 0; q < 4; q++)
                s += smf[GRo + (q * PXT + px) * 36 + p];
            G[p] = s;
        }
        float beta[Gn], alpha[Gn];
        #pragma unroll
        for (int g = 0; g < Gn; g++) {
            float s = 0.f;
            #pragma unroll
            for (int g2 = 0; g2 < Gn; g2++) s += G[pidx(g2, g)];
            beta[g] = 0.5f * s;
        }
        #pragma unroll
        for (int g = 0; g < Gn; g++) alpha[g] = sigmoidf_(beta[g]);
        #pragma unroll
        for (int g = 0; g < Gn; g++) {
            float s = 0.f;
            #pragma unroll
            for (int g2 = 0; g2 < Gn; g2++) s += alpha[g2] * G[pidx(g2, g)];
            beta[g] += s;
        }
        #pragma unroll
        for (int g = 0; g < Gn; g++)
            smf[ALo + g * PXT + px] = sigmoidf_(beta[g]);
    }
    __syncthreads();

    // ---------------- final: out = sum_g alpha*con + bias (from regs) --------
    {
        float* ob = out + (size_t)bi * FOn * HWn + p0;
        #pragma unroll
        for (int r = 0; r < 2; r++) {
            const int pxl = pxb + gid + 8 * r;
            float al[Gn];
            #pragma unroll
            for (int g = 0; g < Gn; g++) al[g] = smf[ALo + g * PXT + pxl];
            #pragma unroll
            for (int n = 0; n < 2; n++) {
                #pragma unroll
                for (int jj = 0; jj < 2; jj++) {
                    float s = 0.f;
                    #pragma unroll
                    for (int g = 0; g < Gn; g++)
                        s += al[g] * acc[g][n][2 * r + jj];
                    int fo = fob + n * 8 + 2 * tid4 + jj;
                    ob[(size_t)fo * HWn + pxl] = s + __ldg(&bias[fo]);
                }
            }
        }
    }
}

extern "C" void kernel_launch(void* const* d_in, const int* in_sizes, int n_in,
                              void* d_out, int out_size)
{
    const float* x = nullptr;
    const float* w = nullptr;
    const float* b = nullptr;
    for (int i = 0; i < n_in; i++) {
        if (in_sizes[i] == Bn * Gn * FIn * HWn)      x = (const float*)d_in[i];
        else if (in_sizes[i] == Gn * FOn * FIn)      w = (const float*)d_in[i];
        else if (in_sizes[i] == FOn)                 b = (const float*)d_in[i];
    }
    float* out = (float*)d_out;

    static bool attr_set = false;
    if (!attr_set) {
        cudaFuncSetAttribute(dynrout_mma_kernel,
                             cudaFuncAttributeMaxDynamicSharedMemorySize, SMEM_BYTES);
        attr_set = true;
    }

    const int n_ctas = (Bn * HWn) / PXT;   // 2048
    dynrout_mma_kernel<<<n_ctas, THREADS, SMEM_BYTES>>>(x, w, b, out);
}

// round 11
// speedup vs baseline: 1.5959x; 1.5054x over previous
#include <cuda_runtime.h>
#include <cstdint>

// DynamicRouting (R10): PXT=32, 256 thr, 2 CTAs/SM. Warp-half group split
// (16px x 32fo warp tiles, 4 iterations). Fully swizzled SMEM (no padding):
// con 512x32 + XOR(4*(row&7)), X 64x32 + XOR(8*(fi&3)), W 64x64 + XOR(4*(fo&7)).
// cp.async loads, tf32 cvt at fragment load, Gram-matrix routing.

namespace {
constexpr int Gn   = 8;
constexpr int FIn  = 64;
constexpr int FOn  = 64;
constexpr int HWn  = 4096;
constexpr int Bn   = 16;
constexpr int PXT  = 32;
constexpr int THREADS = 256;

// word offsets
constexpr int CONo = 0;                        // 512 rows x 32 = 16384 words
constexpr int Xo   = 16384;                    // 2 halves x 64x32 = 4096 words
constexpr int Wo   = Xo + 2 * FIn * PXT;       // 20480: 2 halves x 64x64 = 8192
constexpr int ALo  = Xo;                       // alpha reuses X region (256 w)
constexpr int SMEM_WORDS = Wo + 2 * FOn * FIn; // 28672
constexpr int SMEM_BYTES = SMEM_WORDS * 4;     // 114688 B -> 2 CTAs/SM
}

__device__ __forceinline__ uint32_t cvt_tf32(float f) {
    uint32_t r;
    asm("cvt.rna.tf32.f32 %0, %1;" : "=r"(r) : "f"(f));
    return r;
}

__device__ __forceinline__ uint32_t smem_u32(const void* p) {
    uint32_t a;
    asm("{ .reg .u64 t; cvta.to.shared.u64 t, %1; cvt.u32.u64 %0, t; }"
        : "=r"(a) : "l"(p));
    return a;
}

__device__ __forceinline__ void cp16(uint32_t dst, const void* src) {
    asm volatile("cp.async.cg.shared.global [%0], [%1], 16;"
                 :: "r"(dst), "l"(src) : "memory");
}

__device__ __forceinline__ void mma_tf32(float c[4],
                                         uint32_t a0, uint32_t a1,
                                         uint32_t a2, uint32_t a3,
                                         uint32_t b0, uint32_t b1) {
    asm volatile(
        "mma.sync.aligned.m16n8k8.row.col.f32.tf32.tf32.f32 "
        "{%0,%1,%2,%3}, {%4,%5,%6,%7}, {%8,%9}, {%0,%1,%2,%3};"
        : "+f"(c[0]), "+f"(c[1]), "+f"(c[2]), "+f"(c[3])
        : "r"(a0), "r"(a1), "r"(a2), "r"(a3), "r"(b0), "r"(b1));
}

__device__ __forceinline__ float sigmoidf_(float v) {
    return 1.f / (1.f + __expf(-v));
}

__device__ __forceinline__ int pidx(int a, int b) {
    int lo = a < b ? a : b, hi = a < b ? b : a;
    return lo * 8 - lo * (lo - 1) / 2 + (hi - lo);
}

// swizzled con word address for element (row = g*64+fo, px)
__device__ __forceinline__ int con_addr(int row, int px) {
    return CONo + row * 32 + (px ^ (4 * (row & 7)));
}

__global__ void __launch_bounds__(THREADS, 2)
dynrout_mma_kernel(const float* __restrict__ x,
                   const float* __restrict__ w,
                   const float* __restrict__ bias,
                   float* __restrict__ out)
{
    extern __shared__ uint32_t smu[];
    float* smf = reinterpret_cast<float*>(smu);
    const uint32_t sbase = smem_u32(smu);

    const int t    = threadIdx.x;
    const int wid  = t >> 5;
    const int lane = t & 31;
    const int gid  = lane >> 2;
    const int tid4 = lane & 3;

    const int cta = blockIdx.x;
    const int bi  = cta >> 7;
    const int p0  = (cta & 127) * PXT;

    const int half = wid >> 2;          // 0: even groups, 1: odd groups
    const int w2   = wid & 3;
    const int pxb  = (w2 & 1) * 16;
    const int fob  = (w2 >> 1) * 32;

    // ---------------- cp.async tile loads (both halves, swizzled) ------------
    auto issue_iter = [&](int it) {
        #pragma unroll
        for (int h = 0; h < 2; h++) {
            const int g = 2 * it + h;
            const float* xg = x + ((size_t)(bi * Gn + g) * FIn) * HWn + p0;
            const float* wg = w + (size_t)g * FOn * FIn;
            const uint32_t xo = sbase + (Xo + h * (FIn * PXT)) * 4;
            const uint32_t wo = sbase + (Wo + h * (FOn * FIn)) * 4;
            #pragma unroll
            for (int k = 0; k < 2; k++) {       // X: 512 chunks of 16B
                int q  = t + k * THREADS;
                int fi = q >> 3;
                int c4 = (q & 7) * 4;
                cp16(xo + (fi * 32 + (c4 ^ (8 * (fi & 3)))) * 4,
                     xg + (size_t)fi * HWn + c4);
            }
            #pragma unroll
            for (int k = 0; k < 4; k++) {       // W: 1024 chunks of 16B
                int q  = t + k * THREADS;
                int fo = q >> 4;
                int c4 = (q & 15) * 4;
                cp16(wo + (fo * 64 + (c4 ^ (4 * (fo & 7)))) * 4,
                     wg + fo * FIn + c4);
            }
        }
        asm volatile("cp.async.commit_group;" ::: "memory");
    };

    // ---------------- GEMM: 4 iterations, group = 2*it + half ----------------
    issue_iter(0);

    for (int it = 0; it < 4; it++) {
        asm volatile("cp.async.wait_group 0;" ::: "memory");
        __syncthreads();

        const int g  = 2 * it + half;
        const int xo = Xo + half * (FIn * PXT);
        const int wo = Wo + half * (FOn * FIn);

        float acc[4][4];
        #pragma unroll
        for (int n = 0; n < 4; n++)
            #pragma unroll
            for (int j = 0; j < 4; j++) acc[n][j] = 0.f;

        #pragma unroll
        for (int s = 0; s < 8; s++) {
            const int fi0 = s * 8;
            const int sxa = 8 * tid4;   // (fi&3)==tid4 for both fi rows
            uint32_t a0 = cvt_tf32(smf[xo + (fi0 + tid4)     * 32 + ((pxb + gid)     ^ sxa)]);
            uint32_t a1 = cvt_tf32(smf[xo + (fi0 + tid4)     * 32 + ((pxb + gid + 8) ^ sxa)]);
            uint32_t a2 = cvt_tf32(smf[xo + (fi0 + 4 + tid4) * 32 + ((pxb + gid)     ^ sxa)]);
            uint32_t a3 = cvt_tf32(smf[xo + (fi0 + 4 + tid4) * 32 + ((pxb + gid + 8) ^ sxa)]);
            #pragma unroll
            for (int n = 0; n < 4; n++) {
                const int fo = fob + n * 8 + gid;
                const int sw = 4 * (fo & 7);    // == 4*gid
                uint32_t b0 = cvt_tf32(smf[wo + fo * 64 + ((fi0 + tid4)     ^ sw)]);
                uint32_t b1 = cvt_tf32(smf[wo + fo * 64 + ((fi0 + 4 + tid4) ^ sw)]);
                mma_tf32(acc[n], a0, a1, a2, a3, b0, b1);
            }
        }

        // store con (swizzled, conflict-free)
        #pragma unroll
        for (int n = 0; n < 4; n++) {
            const int fo   = fob + n * 8 + 2 * tid4;
            const int row0 = g * FOn + fo;
            const int row1 = row0 + 1;
            smf[con_addr(row0, pxb + gid)]     = acc[n][0];
            smf[con_addr(row1, pxb + gid)]     = acc[n][1];
            smf[con_addr(row0, pxb + gid + 8)] = acc[n][2];
            smf[con_addr(row1, pxb + gid + 8)] = acc[n][3];
        }

        __syncthreads();
        if (it < 3) issue_iter(it + 1);
    }

    // ---------------- Gram pass (8 threads per px) ---------------------------
    {
        const int px  = t >> 3;             // 0..31
        const int foc = t & 7;              // 8-fo chunk
        float acc[36];
        #pragma unroll
        for (int p = 0; p < 36; p++) acc[p] = 0.f;

        #pragma unroll
        for (int i = 0; i < 8; i++) {
            const int fo = foc * 8 + ((i + foc) & 7);   // stagger: conflict-free
            float cg[Gn];
            #pragma unroll
            for (int g = 0; g < Gn; g++)
                cg[g] = smf[con_addr(g * FOn + fo, px)];
            int p = 0;
            #pragma unroll
            for (int a = 0; a < Gn; a++)
                #pragma unroll
                for (int b = a; b < Gn; b++)
                    acc[p++] += cg[a] * cg[b];
        }
        #pragma unroll
        for (int p = 0; p < 36; p++) {
            acc[p] += __shfl_xor_sync(0xFFFFFFFFu, acc[p], 1);
            acc[p] += __shfl_xor_sync(0xFFFFFFFFu, acc[p], 2);
            acc[p] += __shfl_xor_sync(0xFFFFFFFFu, acc[p], 4);
        }

        // routing on 8x8 Gram (redundant across octet; foc==0 stores alpha)
        float beta[Gn], alpha[Gn];
        #pragma unroll
        for (int g = 0; g < Gn; g++) {
            float s = 0.f;
            #pragma unroll
            for (int g2 = 0; g2 < Gn; g2++) s += acc[pidx(g2, g)];
            beta[g] = 0.5f * s;
        }
        #pragma unroll
        for (int g = 0; g < Gn; g++) alpha[g] = sigmoidf_(beta[g]);
        #pragma unroll
        for (int g = 0; g < Gn; g++) {
            float s = 0.f;
            #pragma unroll
            for (int g2 = 0; g2 < Gn; g2++) s += alpha[g2] * acc[pidx(g2, g)];
            beta[g] += s;
        }
        if (foc == 0) {
            #pragma unroll
            for (int g = 0; g < Gn; g++)
                smf[ALo + g * PXT + px] = sigmoidf_(beta[g]);
        }
    }
    __syncthreads();

    // ---------------- final pass: out = sum_g alpha*con + bias ---------------
    {
        const int px  = t & 31;
        const int foc = t >> 5;             // 0..7
        float al[Gn];
        #pragma unroll
        for (int g = 0; g < Gn; g++) al[g] = smf[ALo + g * PXT + px];

        float* ob = out + (size_t)bi * FOn * HWn + p0;
        #pragma unroll
        for (int i = 0; i < 8; i++) {
            const int fo = foc * 8 + i;
            float s = 0.f;
            #pragma unroll
            for (int g = 0; g < Gn; g++)
                s += al[g] * smf[con_addr(g * FOn + fo, px)];
            ob[(size_t)fo * HWn + px] = s + __ldg(&bias[fo]);
        }
    }
}

extern "C" void kernel_launch(void* const* d_in, const int* in_sizes, int n_in,
                              void* d_out, int out_size)
{
    const float* x = nullptr;
    const float* w = nullptr;
    const float* b = nullptr;
    for (int i = 0; i < n_in; i++) {
        if (in_sizes[i] == Bn * Gn * FIn * HWn)      x = (const float*)d_in[i];
        else if (in_sizes[i] == Gn * FOn * FIn)      w = (const float*)d_in[i];
        else if (in_sizes[i] == FOn)                 b = (const float*)d_in[i];
    }
    float* out = (float*)d_out;

    static bool attr_set = false;
    if (!attr_set) {
        cudaFuncSetAttribute(dynrout_mma_kernel,
                             cudaFuncAttributeMaxDynamicSharedMemorySize, SMEM_BYTES);
        attr_set = true;
    }

    const int n_ctas = (Bn * HWn) / PXT;   // 2048
    dynrout_mma_kernel<<<n_ctas, THREADS, SMEM_BYTES>>>(x, w, b, out);
}

// round 12
// speedup vs baseline: 1.7132x; 1.0735x over previous
#include <cuda_runtime.h>
#include <cstdint>

// DynamicRouting (R11): R10 + (a) W pre-converted to tf32 in a pre-kernel
// (no per-CTA b-cvt), (b) B fragments loaded via ldmatrix.m8n8.x4.b16
// (2 LDSM replace 16 scalar LDS per k-step). A-side and epilogue unchanged.

namespace {
constexpr int Gn   = 8;
constexpr int FIn  = 64;
constexpr int FOn  = 64;
constexpr int HWn  = 4096;
constexpr int Bn   = 16;
constexpr int PXT  = 32;
constexpr int THREADS = 256;

// word offsets
constexpr int CONo = 0;                        // 512 rows x 32 = 16384 words
constexpr int Xo   = 16384;                    // 2 halves x 64x32 = 4096 words
constexpr int Wo   = Xo + 2 * FIn * PXT;       // 20480: 2 halves x 64x64 = 8192
constexpr int ALo  = Xo;                       // alpha reuses X region (256 w)
constexpr int SMEM_WORDS = Wo + 2 * FOn * FIn; // 28672
constexpr int SMEM_BYTES = SMEM_WORDS * 4;     // 114688 B -> 2 CTAs/SM
}

// pre-converted tf32 weights (raw bits), 8*64*64 = 32768 words = 128 KB
__device__ uint32_t g_wtf[Gn * FOn * FIn];

__device__ __forceinline__ uint32_t cvt_tf32(float f) {
    uint32_t r;
    asm("cvt.rna.tf32.f32 %0, %1;" : "=r"(r) : "f"(f));
    return r;
}

__device__ __forceinline__ uint32_t smem_u32(const void* p) {
    uint32_t a;
    asm("{ .reg .u64 t; cvta.to.shared.u64 t, %1; cvt.u32.u64 %0, t; }"
        : "=r"(a) : "l"(p));
    return a;
}

__device__ __forceinline__ void cp16(uint32_t dst, const void* src) {
    asm volatile("cp.async.cg.shared.global [%0], [%1], 16;"
                 :: "r"(dst), "l"(src) : "memory");
}

__device__ __forceinline__ void ldmatrix_x4(uint32_t& r0, uint32_t& r1,
                                            uint32_t& r2, uint32_t& r3,
                                            uint32_t addr) {
    asm volatile("ldmatrix.sync.aligned.m8n8.x4.shared.b16 {%0,%1,%2,%3}, [%4];"
                 : "=r"(r0), "=r"(r1), "=r"(r2), "=r"(r3) : "r"(addr));
}

__device__ __forceinline__ void mma_tf32(float c[4],
                                         uint32_t a0, uint32_t a1,
                                         uint32_t a2, uint32_t a3,
                                         uint32_t b0, uint32_t b1) {
    asm volatile(
        "mma.sync.aligned.m16n8k8.row.col.f32.tf32.tf32.f32 "
        "{%0,%1,%2,%3}, {%4,%5,%6,%7}, {%8,%9}, {%0,%1,%2,%3};"
        : "+f"(c[0]), "+f"(c[1]), "+f"(c[2]), "+f"(c[3])
        : "r"(a0), "r"(a1), "r"(a2), "r"(a3), "r"(b0), "r"(b1));
}

__device__ __forceinline__ float sigmoidf_(float v) {
    return 1.f / (1.f + __expf(-v));
}

__device__ __forceinline__ int pidx(int a, int b) {
    int lo = a < b ? a : b, hi = a < b ? b : a;
    return lo * 8 - lo * (lo - 1) / 2 + (hi - lo);
}

// swizzled con word address for element (row = g*64+fo, px)
__device__ __forceinline__ int con_addr(int row, int px) {
    return CONo + row * 32 + (px ^ (4 * (row & 7)));
}

// ---------------- pre-kernel: W -> tf32 scratch ------------------------------
__global__ void wconv_kernel(const float* __restrict__ w) {
    int i = blockIdx.x * blockDim.x + threadIdx.x;
    g_wtf[i] = cvt_tf32(w[i]);
}

// ---------------- main kernel ------------------------------------------------
__global__ void __launch_bounds__(THREADS, 2)
dynrout_mma_kernel(const float* __restrict__ x,
                   const float* __restrict__ bias,
                   float* __restrict__ out)
{
    extern __shared__ uint32_t smu[];
    float* smf = reinterpret_cast<float*>(smu);
    const uint32_t sbase = smem_u32(smu);

    const int t    = threadIdx.x;
    const int wid  = t >> 5;
    const int lane = t & 31;
    const int gid  = lane >> 2;
    const int tid4 = lane & 3;

    const int cta = blockIdx.x;
    const int bi  = cta >> 7;
    const int p0  = (cta & 127) * PXT;

    const int half = wid >> 2;          // 0: even groups, 1: odd groups
    const int w2   = wid & 3;
    const int pxb  = (w2 & 1) * 16;
    const int fob  = (w2 >> 1) * 32;

    // ldmatrix thread->row mapping (per octet)
    const int oct = lane >> 3;          // 0..3
    const int oo  = oct & 1;            // kq parity
    const int nt  = oct >> 1;           // n-tile within pair
    const int r8  = lane & 7;           // row within 8

    // ---------------- cp.async tile loads (both halves, swizzled) ------------
    auto issue_iter = [&](int it) {
        #pragma unroll
        for (int h = 0; h < 2; h++) {
            const int g = 2 * it + h;
            const float* xg = x + ((size_t)(bi * Gn + g) * FIn) * HWn + p0;
            const uint32_t* wg = g_wtf + g * (FOn * FIn);
            const uint32_t xo = sbase + (Xo + h * (FIn * PXT)) * 4;
            const uint32_t wo = sbase + (Wo + h * (FOn * FIn)) * 4;
            #pragma unroll
            for (int k = 0; k < 2; k++) {       // X: 512 chunks of 16B
                int q  = t + k * THREADS;
                int fi = q >> 3;
                int c4 = (q & 7) * 4;
                cp16(xo + (fi * 32 + (c4 ^ (8 * (fi & 3)))) * 4,
                     xg + (size_t)fi * HWn + c4);
            }
            #pragma unroll
            for (int k = 0; k < 4; k++) {       // W: 1024 chunks of 16B
                int q  = t + k * THREADS;
                int fo = q >> 4;
                int c4 = (q & 15) * 4;
                cp16(wo + (fo * 64 + (c4 ^ (4 * (fo & 7)))) * 4,
                     wg + fo * FIn + c4);
            }
        }
        asm volatile("cp.async.commit_group;" ::: "memory");
    };

    // ---------------- GEMM: 4 iterations, group = 2*it + half ----------------
    issue_iter(0);

    for (int it = 0; it < 4; it++) {
        asm volatile("cp.async.wait_group 0;" ::: "memory");
        __syncthreads();

        const int g  = 2 * it + half;
        const int xo = Xo + half * (FIn * PXT);
        const int wo = Wo + half * (FOn * FIn);

        // ldmatrix per-thread row bases (bytes): n-tiles {0,1} and {2,3}
        const uint32_t bw0 = sbase + (uint32_t)(wo + (fob +      nt * 8 + r8) * 64) * 4;
        const uint32_t bw1 = sbase + (uint32_t)(wo + (fob + 16 + nt * 8 + r8) * 64) * 4;

        float acc[4][4];
        #pragma unroll
        for (int n = 0; n < 4; n++)
            #pragma unroll
            for (int j = 0; j < 4; j++) acc[n][j] = 0.f;

        #pragma unroll
        for (int s = 0; s < 8; s++) {
            const int fi0 = s * 8;
            const int sxa = 8 * tid4;
            uint32_t a0 = cvt_tf32(smf[xo + (fi0 + tid4)     * 32 + ((pxb + gid)     ^ sxa)]);
            uint32_t a1 = cvt_tf32(smf[xo + (fi0 + tid4)     * 32 + ((pxb + gid + 8) ^ sxa)]);
            uint32_t a2 = cvt_tf32(smf[xo + (fi0 + 4 + tid4) * 32 + ((pxb + gid)     ^ sxa)]);
            uint32_t a3 = cvt_tf32(smf[xo + (fi0 + 4 + tid4) * 32 + ((pxb + gid + 8) ^ sxa)]);

            // B fragments: chunk = (2s+oo) ^ r8, 16 bytes each
            const uint32_t coff = 16u * (uint32_t)((2 * s + oo) ^ r8);
            uint32_t b0, b1, b2, b3, b4, b5, b6, b7;
            ldmatrix_x4(b0, b1, b2, b3, bw0 + coff);   // n-tiles 0,1
            ldmatrix_x4(b4, b5, b6, b7, bw1 + coff);   // n-tiles 2,3

            mma_tf32(acc[0], a0, a1, a2, a3, b0, b1);
            mma_tf32(acc[1], a0, a1, a2, a3, b2, b3);
            mma_tf32(acc[2], a0, a1, a2, a3, b4, b5);
            mma_tf32(acc[3], a0, a1, a2, a3, b6, b7);
        }

        // store con (swizzled, conflict-free)
        #pragma unroll
        for (int n = 0; n < 4; n++) {
            const int fo   = fob + n * 8 + 2 * tid4;
            const int row0 = g * FOn + fo;
            const int row1 = row0 + 1;
            smf[con_addr(row0, pxb + gid)]     = acc[n][0];
            smf[con_addr(row1, pxb + gid)]     = acc[n][1];
            smf[con_addr(row0, pxb + gid + 8)] = acc[n][2];
            smf[con_addr(row1, pxb + gid + 8)] = acc[n][3];
        }

        __syncthreads();
        if (it < 3) issue_iter(it + 1);
    }

    // ---------------- Gram pass (8 threads per px) ---------------------------
    {
        const int px  = t >> 3;             // 0..31
        const int foc = t & 7;              // 8-fo chunk
        float acc[36];
        #pragma unroll
        for (int p = 0; p < 36; p++) acc[p] = 0.f;

        #pragma unroll
        for (int i = 0; i < 8; i++) {
            const int fo = foc * 8 + ((i + foc) & 7);   // stagger: conflict-free
            float cg[Gn];
            #pragma unroll
            for (int g = 0; g < Gn; g++)
                cg[g] = smf[con_addr(g * FOn + fo, px)];
            int p = 0;
            #pragma unroll
            for (int a = 0; a < Gn; a++)
                #pragma unroll
                for (int b = a; b < Gn; b++)
                    acc[p++] += cg[a] * cg[b];
        }
        #pragma unroll
        for (int p = 0; p < 36; p++) {
            acc[p] += __shfl_xor_sync(0xFFFFFFFFu, acc[p], 1);
            acc[p] += __shfl_xor_sync(0xFFFFFFFFu, acc[p], 2);
            acc[p] += __shfl_xor_sync(0xFFFFFFFFu, acc[p], 4);
        }

        float beta[Gn], alpha[Gn];
        #pragma unroll
        for (int g = 0; g < Gn; g++) {
            float s = 0.f;
            #pragma unroll
            for (int g2 = 0; g2 < Gn; g2++) s += acc[pidx(g2, g)];
            beta[g] = 0.5f * s;
        }
        #pragma unroll
        for (int g = 0; g < Gn; g++) alpha[g] = sigmoidf_(beta[g]);
        #pragma unroll
        for (int g = 0; g < Gn; g++) {
            float s = 0.f;
            #pragma unroll
            for (int g2 = 0; g2 < Gn; g2++) s += alpha[g2] * acc[pidx(g2, g)];
            beta[g] += s;
        }
        if (foc == 0) {
            #pragma unroll
            for (int g = 0; g < Gn; g++)
                smf[ALo + g * PXT + px] = sigmoidf_(beta[g]);
        }
    }
    __syncthreads();

    // ---------------- final pass: out = sum_g alpha*con + bias ---------------
    {
        const int px  = t & 31;
        const int foc = t >> 5;             // 0..7
        float al[Gn];
        #pragma unroll
        for (int g = 0; g < Gn; g++) al[g] = smf[ALo + g * PXT + px];

        float* ob = out + (size_t)bi * FOn * HWn + p0;
        #pragma unroll
        for (int i = 0; i < 8; i++) {
            const int fo = foc * 8 + i;
            float s = 0.f;
            #pragma unroll
            for (int g = 0; g < Gn; g++)
                s += al[g] * smf[con_addr(g * FOn + fo, px)];
            ob[(size_t)fo * HWn + px] = s + __ldg(&bias[fo]);
        }
    }
}

extern "C" void kernel_launch(void* const* d_in, const int* in_sizes, int n_in,
                              void* d_out, int out_size)
{
    const float* x = nullptr;
    const float* w = nullptr;
    const float* b = nullptr;
    for (int i = 0; i < n_in; i++) {
        if (in_sizes[i] == Bn * Gn * FIn * HWn)      x = (const float*)d_in[i];
        else if (in_sizes[i] == Gn * FOn * FIn)      w = (const float*)d_in[i];
        else if (in_sizes[i] == FOn)                 b = (const float*)d_in[i];
    }
    float* out = (float*)d_out;

    static bool attr_set = false;
    if (!attr_set) {
        cudaFuncSetAttribute(dynrout_mma_kernel,
                             cudaFuncAttributeMaxDynamicSharedMemorySize, SMEM_BYTES);
        attr_set = true;
    }

    wconv_kernel<<<(Gn * FOn * FIn) / 256, 256>>>(w);

    const int n_ctas = (Bn * HWn) / PXT;   // 2048
    dynrout_mma_kernel<<<n_ctas, THREADS, SMEM_BYTES>>>(x, b, out);
}